// round 12
// baseline (speedup 1.0000x reference)
#include <cuda_runtime.h>
#include <cuda_bf16.h>
#include <cstdint>

// Problem constants
#define BB   4
#define LL   2048
#define DM   1024
#define KH   32        // heads
#define HD   32        // head dim
#define MT   4         // m_theta
#define TOT  2080      // 2*DM + KH
#define CONVK 4
#define ANCHOR 4
#define TT   8         // scan tile (time steps per tile)
#define NC   32        // scan chunks
#define CL   (LL / NC) // 64 steps per chunk

// K-permutation within 8-groups: original index i stored at pos (i&3)*2+(i>>2)
// so fragment k-pairs (tig, tig+4) land at adjacent words (2*tig, 2*tig+1).

// Scratch (static device globals — no runtime allocation allowed)
__device__ float g_z   [BB * LL * TOT];   // x @ W_in
__device__ float g_zc  [BB * LL * TOT];   // after causal depthwise conv
__device__ float g_g   [BB * LL * DM];    // gated y, tf32-rounded, K-permuted
__device__ float g_x32 [BB * LL * DM];    // x rounded to tf32, K-permuted
__device__ float g_bt1 [TOT * DM];        // W_in^T, K-major, tf32, K-permuted
__device__ float g_bt2 [DM * DM];         // W_out^T, tf32, K-permuted
__device__ float g_btp [32 * 256];        // [W_re;W_im]^T (32 x 256), tf32 (unpermuted)
__device__ float g_part[BB * KH * NC * 3 * 128];  // chunk partials / prefixes

// ---------------------------------------------------------------------------
// TF32 helpers
// ---------------------------------------------------------------------------
__device__ __forceinline__ uint32_t f2tf(float f) {
    uint32_t u;
    asm("cvt.rna.tf32.f32 %0, %1;" : "=r"(u) : "f"(f));
    return u;
}
__device__ __forceinline__ float f2tf_f(float f) {
    return __uint_as_float(f2tf(f));
}

__device__ __forceinline__ void mma_tf32(float* c4, const uint32_t* a4,
                                         const uint32_t* b2) {
    asm volatile(
        "mma.sync.aligned.m16n8k8.row.col.f32.tf32.tf32.f32 "
        "{%0,%1,%2,%3}, {%4,%5,%6,%7}, {%8,%9}, {%0,%1,%2,%3};"
        : "+f"(c4[0]), "+f"(c4[1]), "+f"(c4[2]), "+f"(c4[3])
        : "r"(a4[0]), "r"(a4[1]), "r"(a4[2]), "r"(a4[3]),
          "r"(b2[0]), "r"(b2[1]));
}

__device__ __forceinline__ uint32_t smem_u32(const void* p) {
    uint32_t a;
    asm("{ .reg .u64 t; cvta.to.shared.u64 t, %1; cvt.u32.u64 %0, t; }"
        : "=r"(a) : "l"(p));
    return a;
}
__device__ __forceinline__ void cpa16(uint32_t d, const void* s, int sz) {
    asm volatile("cp.async.cg.shared.global [%0], [%1], 16, %2;"
                 :: "r"(d), "l"(s), "r"(sz));
}
#define CP_COMMIT() asm volatile("cp.async.commit_group;" ::: "memory")
#define CP_WAIT1()  asm volatile("cp.async.wait_group 1;" ::: "memory")

// ---------------------------------------------------------------------------
// Round fp32 -> tf32 (RNA) AND apply K-permutation within 8-float groups.
// Each thread handles one 8-group. n8 = element count / 8.
// out[0..3] = (in0,in4,in1,in5); out[4..7] = (in2,in6,in3,in7).
// ---------------------------------------------------------------------------
__global__ __launch_bounds__(256) void round_perm_k(
    const float4* __restrict__ src, float4* __restrict__ dst, int n8)
{
    int i = blockIdx.x * 256 + threadIdx.x;
    if (i < n8) {
        float4 a = src[i * 2];
        float4 b = src[i * 2 + 1];
        dst[i * 2]     = make_float4(f2tf_f(a.x), f2tf_f(b.x),
                                     f2tf_f(a.y), f2tf_f(b.y));
        dst[i * 2 + 1] = make_float4(f2tf_f(a.z), f2tf_f(b.z),
                                     f2tf_f(a.w), f2tf_f(b.w));
    }
}

// ---------------------------------------------------------------------------
// Tiled transpose with tf32 rounding + K-permutation on the output column:
//   D[r][perm(c)] = round_tf32(S[c][r]) for the K dim (R must be %8==0).
// ---------------------------------------------------------------------------
__global__ __launch_bounds__(256) void transpose_k(
    const float* __restrict__ S, float* __restrict__ D, int R, int C)
{
    __shared__ float t[32][33];
    int c0 = blockIdx.x * 32, r0 = blockIdx.y * 32;
    int x = threadIdx.x & 31, y = threadIdx.x >> 5;   // 32 x 8
#pragma unroll
    for (int i = 0; i < 32; i += 8) {
        int r = r0 + y + i, c = c0 + x;
        t[y + i][x] = (r < R && c < C) ? S[(size_t)r * C + c] : 0.0f;
    }
    __syncthreads();
#pragma unroll
    for (int i = 0; i < 32; i += 8) {
        int r = c0 + y + i, c = r0 + x;
        if (r < C && c < R) {
            int cp = (c & ~7) | (((c & 3) << 1) | ((c >> 2) & 1));
            D[(size_t)r * R + cp] = f2tf_f(t[x][y + i]);
        }
    }
}

// ---------------------------------------------------------------------------
// Projection weight prep: Bt(32 x 256), Bt[n][kk] = [W_re;W_im][kk][n]
// (unpermuted — part3's in-SMEM projection uses the scalar fragment path)
// ---------------------------------------------------------------------------
__global__ __launch_bounds__(256) void proj_wprep(
    const float* __restrict__ Wre, const float* __restrict__ Wim,
    float* __restrict__ Bt)
{
    int i = blockIdx.x * 256 + threadIdx.x;
    if (i < 32 * 256) {
        int n = i >> 8, kk = i & 255;
        float v = (kk < 128) ? Wre[kk * 32 + n] : Wim[(kk - 128) * 32 + n];
        Bt[i] = f2tf_f(v);
    }
}

// ---------------------------------------------------------------------------
// TF32 tensor-core GEMM, cp.async 3-stage pipeline, K-permuted operands:
//   C(M,Nn) = A(M,Kd) * Bt(Nn,Kd)^T; A and Bt pre-rounded+permuted.
// Fragment loads are LDS.64 (adjacent k-pair after permutation).
// ---------------------------------------------------------------------------
#define GKC 32
#define STAGE_BYTES 32768
#define GEMM_SMEM  (3 * STAGE_BYTES)

__global__ __launch_bounds__(256, 2) void gemm_cp(
    const float* __restrict__ A, const float* __restrict__ Bt,
    float* __restrict__ C, int M, int Nn, int Kd)
{
    extern __shared__ float smem[];
    const uint32_t sbase = smem_u32(smem);
    const int tid = threadIdx.x;
    const int wid = tid >> 5, lane = tid & 31;
    const int gid = lane >> 2, tig = lane & 3;
    const int wm = (wid >> 1) * 32;
    const int wn = (wid & 1) * 64;
    const int row0 = blockIdx.y * 128;
    const int col0 = blockIdx.x * 128;
    const int NCH = Kd / GKC;

    float acc[2][8][4];
#pragma unroll
    for (int mi = 0; mi < 2; ++mi)
#pragma unroll
        for (int ni = 0; ni < 8; ++ni)
#pragma unroll
            for (int q = 0; q < 4; ++q) acc[mi][ni][q] = 0.0f;

    int prow[4], pseg[4];
    uint32_t poff[4];
#pragma unroll
    for (int i = 0; i < 4; ++i) {
        int idx = i * 256 + tid;
        prow[i] = idx >> 3;
        pseg[i] = idx & 7;
        poff[i] = (uint32_t)(prow[i] * 128 + ((pseg[i] ^ (prow[i] & 7)) << 4));
    }

#define PREFETCH(pc) do {                                                     \
    if ((pc) < NCH) {                                                         \
        int k0 = (pc) * GKC;                                                  \
        uint32_t stb = sbase + ((pc) % 3) * STAGE_BYTES;                      \
        _Pragma("unroll")                                                     \
        for (int i = 0; i < 4; ++i) {                                         \
            cpa16(stb + poff[i],                                              \
                  A + (size_t)(row0 + prow[i]) * Kd + k0 + pseg[i] * 4, 16);  \
            int nr = col0 + prow[i];                                          \
            int ok = (nr < Nn);                                               \
            cpa16(stb + 16384 + poff[i],                                      \
                  Bt + (size_t)(ok ? nr : 0) * Kd + k0 + pseg[i] * 4,         \
                  ok ? 16 : 0);                                               \
        }                                                                     \
    }                                                                         \
    CP_COMMIT();                                                              \
} while (0)

    PREFETCH(0);
    PREFETCH(1);

    for (int c = 0; c < NCH; ++c) {
        CP_WAIT1();
        __syncthreads();
        PREFETCH(c + 2);

        const float* Af = smem + (c % 3) * 8192;
        const float* Bf = Af + 4096;

#pragma unroll
        for (int kk = 0; kk < 4; ++kk) {
            // after permutation: k-pair (tig, tig+4) is at words
            // (8kk + 2*tig, 8kk + 2*tig + 1) -> seg 2kk+(tig>>1), half (tig&1)
            const int sA = 2 * kk + (tig >> 1);
            const int o8 = (tig & 1) * 2;   // float offset of 8B half

            uint32_t af[2][4];
#pragma unroll
            for (int mi = 0; mi < 2; ++mi) {
                int ra = wm + mi * 16 + gid;
                float2 lo = *(const float2*)&Af[ra * 32 + ((sA ^ (ra & 7)) << 2) + o8];
                int rb = ra + 8;
                float2 hi = *(const float2*)&Af[rb * 32 + ((sA ^ (rb & 7)) << 2) + o8];
                af[mi][0] = __float_as_uint(lo.x);
                af[mi][2] = __float_as_uint(lo.y);
                af[mi][1] = __float_as_uint(hi.x);
                af[mi][3] = __float_as_uint(hi.y);
            }
            uint32_t bf[8][2];
#pragma unroll
            for (int ni = 0; ni < 8; ++ni) {
                int rb = wn + ni * 8 + gid;
                float2 bv = *(const float2*)&Bf[rb * 32 + ((sA ^ (rb & 7)) << 2) + o8];
                bf[ni][0] = __float_as_uint(bv.x);
                bf[ni][1] = __float_as_uint(bv.y);
            }
#pragma unroll
            for (int mi = 0; mi < 2; ++mi)
#pragma unroll
                for (int ni = 0; ni < 8; ++ni)
                    mma_tf32(acc[mi][ni], af[mi], bf[ni]);
        }
    }
#undef PREFETCH

#pragma unroll
    for (int mi = 0; mi < 2; ++mi) {
        int r0 = row0 + wm + mi * 16 + gid;
#pragma unroll
        for (int ni = 0; ni < 8; ++ni) {
            int cc = col0 + wn + ni * 8 + tig * 2;
            if (cc < Nn) {
                *(float2*)(C + (size_t)r0 * Nn + cc) =
                    make_float2(acc[mi][ni][0], acc[mi][ni][1]);
                *(float2*)(C + (size_t)(r0 + 8) * Nn + cc) =
                    make_float2(acc[mi][ni][2], acc[mi][ni][3]);
            }
        }
    }
}

// ---------------------------------------------------------------------------
// Causal depthwise conv1d, kernel 4, left pad 3 — float4 over channels.
// ---------------------------------------------------------------------------
#define TOT4 (TOT / 4)
__global__ __launch_bounds__(256) void conv_kernel(
    const float4* __restrict__ z, const float4* __restrict__ wc,
    const float4* __restrict__ bc, float4* __restrict__ zc)
{
    int idx = blockIdx.x * 256 + threadIdx.x;
    const int total = BB * LL * TOT4;
    if (idx >= total) return;
    int c  = idx % TOT4;
    int bl = idx / TOT4;
    int l  = bl % LL;

    float4 acc = bc[c];
#pragma unroll
    for (int jk = 0; jk < CONVK; ++jk) {
        int ls = l - 3 + jk;
        if (ls >= 0) {
            float4 w = wc[jk * TOT4 + c];
            float4 v = z[(size_t)(bl - 3 + jk) * TOT4 + c];
            acc.x += w.x * v.x; acc.y += w.y * v.y;
            acc.z += w.z * v.z; acc.w += w.w * v.w;
        }
    }
    zc[idx] = acc;
}

// ---------------------------------------------------------------------------
// Shared per-thread scan preamble
// ---------------------------------------------------------------------------
struct ScanConst {
    float theta_t, w0, w1, w2, ss, rate;
    bool decay;
};

__device__ __forceinline__ ScanConst scan_consts(
    int k, int j, const float* theta, const float* dslopes,
    const float* aslopes, const float* sscale, const float* dlogits)
{
    ScanConst sc;
    sc.theta_t = theta[k * (HD * MT) + j];
    float dl0 = dlogits[0], dl1 = dlogits[1], dl2 = dlogits[2];
    float mx = fmaxf(dl0, fmaxf(dl1, dl2));
    float e0 = __expf(dl0 - mx), e1 = __expf(dl1 - mx), e2 = __expf(dl2 - mx);
    float dinv = 1.0f / (e0 + e1 + e2);
    sc.w0 = e0 * dinv; sc.w1 = e1 * dinv; sc.w2 = e2 * dinv;
    sc.ss = sscale[k];
    sc.decay = (k < KH - ANCHOR);
    float slope = sc.decay ? dslopes[k] : aslopes[k - (KH - ANCHOR)];
    sc.rate = logf(1.0f + expf(slope));
    return sc;
}

__device__ __forceinline__ void scan_step(
    const ScanConst& sc, float xv, float sv, float tw,
    float& accRe, float& accIm, float& accDen)
{
    float parg = fminf(fmaxf(sc.ss * sv, -20.0f), 20.0f);
    float p = __expf(parg);
    float pw = p * tw;
    float phi = xv * sc.theta_t;
    float sbv, cbv;
    __sincosf(phi, &sbv, &cbv);
    float poly = sc.w0 + sc.w1 * xv - sc.w2 * xv * xv;
    float ppw = pw * poly;
    accDen += pw;
    accRe  += ppw * cbv;
    accIm  += ppw * sbv;
}

__device__ __forceinline__ void tw_init(const ScanConst& sc, int lstart,
                                        float& tw, float& twm)
{
    if (sc.decay) {
        tw  = __expf(-sc.rate * (float)(LL - 1 - lstart));
        twm = __expf(sc.rate);
    } else {
        tw  = __expf(-sc.rate * (float)lstart);
        twm = __expf(-sc.rate);
    }
}

// ---------------------------------------------------------------------------
// Scan pass 1: per-chunk lane sums from zc. grid = B*K*NC, block = 128.
// ---------------------------------------------------------------------------
__global__ __launch_bounds__(128) void scan_part1(
    const float* __restrict__ zc, const float* __restrict__ theta,
    const float* __restrict__ dslopes, const float* __restrict__ aslopes,
    const float* __restrict__ sscale, const float* __restrict__ dlogits,
    float* __restrict__ part)
{
    __shared__ float sxv[CL * 32];
    __shared__ float ssv[CL];

    const int chunk = blockIdx.x % NC;
    const int bk    = blockIdx.x / NC;
    const int k  = bk % KH;
    const int bb = bk / KH;
    const int tid = threadIdx.x;
    const int j = tid, h = j >> 2;

    const ScanConst sc = scan_consts(k, j, theta, dslopes, aslopes, sscale, dlogits);
    float tw, twm;
    tw_init(sc, chunk * CL, tw, twm);

    const size_t baserow = (size_t)bb * LL;
    const int l0 = chunk * CL;

    for (int i = tid; i < CL * 32; i += 128) {
        int r = i >> 5, hh = i & 31;
        sxv[i] = zc[(baserow + l0 + r) * (size_t)TOT + (size_t)k * HD + hh];
    }
    if (tid < CL)
        ssv[tid] = zc[(baserow + l0 + tid) * (size_t)TOT + 2 * DM + k];
    __syncthreads();

    float accRe = 0.0f, accIm = 0.0f, accDen = 0.0f;
#pragma unroll 4
    for (int t = 0; t < CL; ++t) {
        scan_step(sc, sxv[t * 32 + h], ssv[t], tw, accRe, accIm, accDen);
        tw *= twm;
    }

    float* p = part + (size_t)blockIdx.x * 384;
    p[j] = accRe; p[128 + j] = accIm; p[256 + j] = accDen;
}

// ---------------------------------------------------------------------------
// Scan pass 2: exclusive prefix over chunks, in place. grid = B*K, block 128.
// ---------------------------------------------------------------------------
__global__ __launch_bounds__(128) void scan_part2(float* __restrict__ part)
{
    const int bk = blockIdx.x;
    const int j = threadIdx.x;
    float rRe = 0.0f, rIm = 0.0f, rDen = 0.0f;
    for (int c = 0; c < NC; ++c) {
        float* p = part + ((size_t)bk * NC + c) * 384;
        float tRe = p[j], tIm = p[128 + j], tDen = p[256 + j];
        p[j] = rRe; p[128 + j] = rIm; p[256 + j] = rDen;
        rRe += tRe; rIm += tIm; rDen += tDen;
    }
}

// ---------------------------------------------------------------------------
// Scan pass 3 (fused): scan + joint RMS norm + in-SMEM projection GEMM
// (mma.sync) + SiLU gate. Writes g (K-permuted for GEMM2).
// ---------------------------------------------------------------------------
#define P3_WS   0
#define P3_AS   (32 * 260)                 // 8320
#define P3_SSQ  (P3_AS + 16 * 260)         // 12480
#define P3_SXV  (P3_SSQ + TT * 128)        // 13504
#define P3_SGV  (P3_SXV + TT * 32)         // 13760
#define P3_SSV  (P3_SGV + 16 * 32)         // 14272
#define P3_SRSQ (P3_SSV + TT)              // 14280
#define P3_SMEM ((P3_SRSQ + TT) * 4)       // 57152 bytes

__global__ __launch_bounds__(128) void scan_part3(
    const float* __restrict__ zc, const float* __restrict__ theta,
    const float* __restrict__ dslopes, const float* __restrict__ aslopes,
    const float* __restrict__ sscale, const float* __restrict__ dlogits,
    const float* __restrict__ nscale, const float* __restrict__ Wp,
    const float* __restrict__ part, float* __restrict__ g_out)
{
    extern __shared__ float sm[];
    float* Ws   = sm + P3_WS;
    float* As   = sm + P3_AS;
    float* ssq  = sm + P3_SSQ;
    float* sxv  = sm + P3_SXV;
    float* sgv  = sm + P3_SGV;
    float* ssv  = sm + P3_SSV;
    float* srsq = sm + P3_SRSQ;

    const int chunk = blockIdx.x % NC;
    const int bk    = blockIdx.x / NC;
    const int k  = bk % KH;
    const int bb = bk / KH;
    const int tid = threadIdx.x;
    const int j = tid, h = j >> 2;
    const int lane = tid & 31;
    const int warp = tid >> 5;
    const int gid = lane >> 2, tig = lane & 3;

    const ScanConst sc = scan_consts(k, j, theta, dslopes, aslopes, sscale, dlogits);
    const float ns_re = nscale[j];
    const float ns_im = nscale[HD * MT + j];
    float tw, twm;
    tw_init(sc, chunk * CL, tw, twm);

    // load projection weights (32 x 256) into padded smem
    for (int i = tid; i < 32 * 256; i += 128) {
        int row = i >> 8, col = i & 255;
        Ws[row * 260 + col] = Wp[i];
    }

    const float* pfx = part + (size_t)blockIdx.x * 384;
    float accRe = pfx[j], accIm = pfx[128 + j], accDen = pfx[256 + j];
    const size_t baserow = (size_t)bb * LL;

    // permuted in-group positions for this thread's two output channels
    const int i0 = tig * 2, i1 = tig * 2 + 1;
    const int p0 = ((i0 & 3) << 1) | (i0 >> 2);
    const int p1 = ((i1 & 3) << 1) | (i1 >> 2);

    for (int grp = 0; grp < CL / 16; ++grp) {
        const int gl0 = chunk * CL + grp * 16;

#pragma unroll
        for (int sub = 0; sub < 2; ++sub) {
            const int l0 = gl0 + sub * TT;
            __syncthreads();
            {
                int v = tid;
                int t = v >> 5, hh = v & 31;
                size_t rowA = (baserow + l0 + t) * (size_t)TOT;
                sxv[v] = zc[rowA + (size_t)k * HD + hh];
                sgv[(sub * TT + t) * 32 + hh] = zc[rowA + DM + (size_t)k * HD + hh];
                v = tid + 128; t = v >> 5; hh = v & 31;
                size_t rowB = (baserow + l0 + t) * (size_t)TOT;
                sxv[v] = zc[rowB + (size_t)k * HD + hh];
                sgv[(sub * TT + t) * 32 + hh] = zc[rowB + DM + (size_t)k * HD + hh];
                if (tid < TT)
                    ssv[tid] = zc[(baserow + l0 + tid) * (size_t)TOT + 2 * DM + k];
            }
            __syncthreads();

            float re[TT], im[TT];
#pragma unroll
            for (int t = 0; t < TT; ++t) {
                scan_step(sc, sxv[t * 32 + h], ssv[t], tw, accRe, accIm, accDen);
                tw *= twm;
                float invd = 1.0f / fmaxf(accDen, 1e-4f);
                re[t] = accRe * invd;
                im[t] = accIm * invd;
                ssq[t * 128 + j] = re[t] * re[t] + im[t] * im[t];
            }
            __syncthreads();

            {
                int tt = warp * 2;
#pragma unroll
                for (int q = 0; q < 2; ++q, ++tt) {
                    float v = ssq[tt * 128 + lane] + ssq[tt * 128 + lane + 32]
                            + ssq[tt * 128 + lane + 64] + ssq[tt * 128 + lane + 96];
#pragma unroll
                    for (int off = 16; off; off >>= 1)
                        v += __shfl_xor_sync(0xffffffffu, v, off);
                    if (lane == 0)
                        srsq[tt] = rsqrtf(v * (1.0f / (2.0f * HD * MT)) + 1e-5f);
                }
            }
            __syncthreads();

#pragma unroll
            for (int t = 0; t < TT; ++t) {
                float r = srsq[t];
                int row = sub * TT + t;
                As[row * 260 + j]       = f2tf_f(re[t] * r * ns_re);
                As[row * 260 + 128 + j] = f2tf_f(im[t] * r * ns_im);
            }
        }
        __syncthreads();   // As tile (16 x 256) complete

        // projection: C(16 x 32) = As(16 x 256) @ Ws(32 x 256)^T
        float acc[4] = {0.0f, 0.0f, 0.0f, 0.0f};
#pragma unroll
        for (int ks = 0; ks < 32; ++ks) {
            int kb = ks * 8;
            uint32_t af[4], bf[2];
            int abase = gid * 260 + kb + tig;
            af[0] = __float_as_uint(As[abase]);
            af[1] = __float_as_uint(As[abase + 8 * 260]);
            af[2] = __float_as_uint(As[abase + 4]);
            af[3] = __float_as_uint(As[abase + 8 * 260 + 4]);
            int bbase = (warp * 8 + gid) * 260 + kb + tig;
            bf[0] = __float_as_uint(Ws[bbase]);
            bf[1] = __float_as_uint(Ws[bbase + 4]);
            mma_tf32(acc, af, bf);
        }

        // epilogue: gate + tf32 round + K-permuted store to g
#pragma unroll
        for (int rg = 0; rg < 2; ++rg) {
            int m = gid + rg * 8;           // step within group
            int l = gl0 + m;
            int hh = warp * 8 + tig * 2;
            float gz0 = sgv[m * 32 + hh];
            float gz1 = sgv[m * 32 + hh + 1];
            float s0 = gz0 / (1.0f + __expf(-gz0));
            float s1 = gz1 / (1.0f + __expf(-gz1));
            float* gb = g_out + (baserow + l) * (size_t)DM
                      + (size_t)k * HD + warp * 8;
            gb[p0] = f2tf_f(acc[rg * 2 + 0] * s0);
            gb[p1] = f2tf_f(acc[rg * 2 + 1] * s1);
        }
    }
}

// ---------------------------------------------------------------------------
extern "C" void kernel_launch(void* const* d_in, const int* in_sizes, int n_in,
                              void* d_out, int out_size)
{
    const float* x       = (const float*)d_in[0];
    const float* W_in    = (const float*)d_in[1];
    const float* w_conv  = (const float*)d_in[2];
    const float* b_conv  = (const float*)d_in[3];
    const float* theta   = (const float*)d_in[4];
    const float* dslopes = (const float*)d_in[5];
    const float* aslopes = (const float*)d_in[6];
    const float* sscale  = (const float*)d_in[7];
    const float* dlogits = (const float*)d_in[8];
    const float* nscale  = (const float*)d_in[9];
    const float* W_re    = (const float*)d_in[10];
    const float* W_im    = (const float*)d_in[11];
    const float* W_out   = (const float*)d_in[12];
    float* out = (float*)d_out;

    float *pz, *pzc, *pg, *px32, *pbt1, *pbt2, *pbtp, *ppart;
    cudaGetSymbolAddress((void**)&pz,    g_z);
    cudaGetSymbolAddress((void**)&pzc,   g_zc);
    cudaGetSymbolAddress((void**)&pg,    g_g);
    cudaGetSymbolAddress((void**)&px32,  g_x32);
    cudaGetSymbolAddress((void**)&pbt1,  g_bt1);
    cudaGetSymbolAddress((void**)&pbt2,  g_bt2);
    cudaGetSymbolAddress((void**)&pbtp,  g_btp);
    cudaGetSymbolAddress((void**)&ppart, g_part);

    static bool attr_set = false;
    if (!attr_set) {
        cudaFuncSetAttribute(gemm_cp,
                             cudaFuncAttributeMaxDynamicSharedMemorySize, GEMM_SMEM);
        cudaFuncSetAttribute(scan_part3,
                             cudaFuncAttributeMaxDynamicSharedMemorySize, P3_SMEM);
        attr_set = true;
    }

    // 0) weight prep + x rounding (all K-permuted for the GEMMs)
    transpose_k<<<dim3((TOT + 31) / 32, DM / 32), 256>>>(W_in, pbt1, DM, TOT);
    transpose_k<<<dim3(DM / 32, DM / 32), 256>>>(W_out, pbt2, DM, DM);
    proj_wprep<<<32, 256>>>(W_re, W_im, pbtp);
    {
        int n8 = BB * LL * DM / 8;
        round_perm_k<<<(n8 + 255) / 256, 256>>>((const float4*)x, (float4*)px32, n8);
    }

    // 1) z = x @ W_in   — TF32 mma.sync, cp.async pipeline, LDS.64 fragments
    {
        dim3 grid((TOT + 127) / 128, (BB * LL) / 128);
        gemm_cp<<<grid, 256, GEMM_SMEM>>>(px32, pbt1, pz, BB * LL, TOT, DM);
    }
    // 2) causal depthwise conv (float4)
    {
        int total = BB * LL * TOT4;
        conv_kernel<<<(total + 255) / 256, 256>>>(
            (const float4*)pz, (const float4*)w_conv,
            (const float4*)b_conv, (float4*)pzc);
    }
    // 3) chunked parallel scan; part3 fuses RMS norm + projection + gate
    scan_part1<<<BB * KH * NC, 128>>>(pzc, theta, dslopes, aslopes,
                                      sscale, dlogits, ppart);
    scan_part2<<<BB * KH, 128>>>(ppart);
    scan_part3<<<BB * KH * NC, 128, P3_SMEM>>>(pzc, theta, dslopes, aslopes,
                                               sscale, dlogits, nscale,
                                               pbtp, ppart, pg);
    // 4) out = g @ W_out — TF32 mma.sync, cp.async pipeline, LDS.64 fragments
    {
        dim3 grid(DM / 128, (BB * LL) / 128);
        gemm_cp<<<grid, 256, GEMM_SMEM>>>(pg, pbt2, out, BB * LL, DM, DM);
    }
}

// round 13
// speedup vs baseline: 1.0727x; 1.0727x over previous
#include <cuda_runtime.h>
#include <cuda_bf16.h>
#include <cstdint>

// Problem constants
#define BB   4
#define LL   2048
#define DM   1024
#define KH   32        // heads
#define HD   32        // head dim
#define MT   4         // m_theta
#define TOT  2080      // 2*DM + KH
#define CONVK 4
#define ANCHOR 4
#define TT   8         // scan tile (time steps per tile)
#define NC   32        // scan chunks
#define CL   (LL / NC) // 64 steps per chunk

// Scratch (static device globals — no runtime allocation allowed)
__device__ float g_z   [BB * LL * TOT];   // x @ W_in
__device__ float g_zc  [BB * LL * TOT];   // after causal depthwise conv
__device__ float g_g   [BB * LL * DM];    // gated y (input to final GEMM), tf32-rounded
__device__ float g_x32 [BB * LL * DM];    // x rounded to tf32
__device__ float g_bt1 [TOT * DM];        // W_in^T  (2080 x 1024), K-major, tf32-rounded
__device__ float g_bt2 [DM * DM];         // W_out^T (1024 x 1024), tf32-rounded
__device__ float g_btp [32 * 256];        // [W_re;W_im]^T (32 x 256), tf32-rounded
__device__ float g_part[BB * KH * NC * 3 * 128];  // chunk partials / prefixes

// ---------------------------------------------------------------------------
// TF32 helpers
// ---------------------------------------------------------------------------
__device__ __forceinline__ uint32_t f2tf(float f) {
    uint32_t u;
    asm("cvt.rna.tf32.f32 %0, %1;" : "=r"(u) : "f"(f));
    return u;
}
__device__ __forceinline__ float f2tf_f(float f) {
    return __uint_as_float(f2tf(f));
}

__device__ __forceinline__ void mma_tf32(float* c4, const uint32_t* a4,
                                         const uint32_t* b2) {
    asm volatile(
        "mma.sync.aligned.m16n8k8.row.col.f32.tf32.tf32.f32 "
        "{%0,%1,%2,%3}, {%4,%5,%6,%7}, {%8,%9}, {%0,%1,%2,%3};"
        : "+f"(c4[0]), "+f"(c4[1]), "+f"(c4[2]), "+f"(c4[3])
        : "r"(a4[0]), "r"(a4[1]), "r"(a4[2]), "r"(a4[3]),
          "r"(b2[0]), "r"(b2[1]));
}

__device__ __forceinline__ uint32_t smem_u32(const void* p) {
    uint32_t a;
    asm("{ .reg .u64 t; cvta.to.shared.u64 t, %1; cvt.u32.u64 %0, t; }"
        : "=r"(a) : "l"(p));
    return a;
}
__device__ __forceinline__ void cpa16(uint32_t d, const void* s, int sz) {
    asm volatile("cp.async.cg.shared.global [%0], [%1], 16, %2;"
                 :: "r"(d), "l"(s), "r"(sz));
}
#define CP_COMMIT() asm volatile("cp.async.commit_group;" ::: "memory")
#define CP_WAIT1()  asm volatile("cp.async.wait_group 1;" ::: "memory")

// ---------------------------------------------------------------------------
// Round fp32 array to tf32 (RNA), vectorized.
// ---------------------------------------------------------------------------
__global__ __launch_bounds__(256) void round_tf32_k(
    const float4* __restrict__ src, float4* __restrict__ dst, int n4)
{
    int i = blockIdx.x * 256 + threadIdx.x;
    if (i < n4) {
        float4 v = src[i];
        v.x = f2tf_f(v.x); v.y = f2tf_f(v.y);
        v.z = f2tf_f(v.z); v.w = f2tf_f(v.w);
        dst[i] = v;
    }
}

// ---------------------------------------------------------------------------
// Tiled transpose with tf32 rounding: D[C][R] = round_tf32(S[R][C]^T)
// ---------------------------------------------------------------------------
__global__ __launch_bounds__(256) void transpose_k(
    const float* __restrict__ S, float* __restrict__ D, int R, int C)
{
    __shared__ float t[32][33];
    int c0 = blockIdx.x * 32, r0 = blockIdx.y * 32;
    int x = threadIdx.x & 31, y = threadIdx.x >> 5;   // 32 x 8
#pragma unroll
    for (int i = 0; i < 32; i += 8) {
        int r = r0 + y + i, c = c0 + x;
        t[y + i][x] = (r < R && c < C) ? S[(size_t)r * C + c] : 0.0f;
    }
    __syncthreads();
#pragma unroll
    for (int i = 0; i < 32; i += 8) {
        int r = c0 + y + i, c = r0 + x;
        if (r < C && c < R) D[(size_t)r * R + c] = f2tf_f(t[x][y + i]);
    }
}

// ---------------------------------------------------------------------------
// Projection weight prep: Bt(32 x 256), Bt[n][kk] = [W_re;W_im][kk][n]
// ---------------------------------------------------------------------------
__global__ __launch_bounds__(256) void proj_wprep(
    const float* __restrict__ Wre, const float* __restrict__ Wim,
    float* __restrict__ Bt)
{
    int i = blockIdx.x * 256 + threadIdx.x;
    if (i < 32 * 256) {
        int n = i >> 8, kk = i & 255;
        float v = (kk < 128) ? Wre[kk * 32 + n] : Wim[(kk - 128) * 32 + n];
        Bt[i] = f2tf_f(v);
    }
}

// ---------------------------------------------------------------------------
// TF32 tensor-core GEMM, cp.async 3-stage pipeline (frozen R5/R7 version):
//   C(M,Nn) = A(M,Kd) * Bt(Nn,Kd)^T; A and Bt pre-rounded to tf32.
// ---------------------------------------------------------------------------
#define GKC 32
#define STAGE_BYTES 32768
#define GEMM_SMEM  (3 * STAGE_BYTES)

__global__ __launch_bounds__(256, 2) void gemm_cp(
    const float* __restrict__ A, const float* __restrict__ Bt,
    float* __restrict__ C, int M, int Nn, int Kd)
{
    extern __shared__ float smem[];
    const uint32_t sbase = smem_u32(smem);
    const int tid = threadIdx.x;
    const int wid = tid >> 5, lane = tid & 31;
    const int gid = lane >> 2, tig = lane & 3;
    const int wm = (wid >> 1) * 32;
    const int wn = (wid & 1) * 64;
    const int row0 = blockIdx.y * 128;
    const int col0 = blockIdx.x * 128;
    const int NCH = Kd / GKC;

    float acc[2][8][4];
#pragma unroll
    for (int mi = 0; mi < 2; ++mi)
#pragma unroll
        for (int ni = 0; ni < 8; ++ni)
#pragma unroll
            for (int q = 0; q < 4; ++q) acc[mi][ni][q] = 0.0f;

    int prow[4], pseg[4];
    uint32_t poff[4];
#pragma unroll
    for (int i = 0; i < 4; ++i) {
        int idx = i * 256 + tid;
        prow[i] = idx >> 3;
        pseg[i] = idx & 7;
        poff[i] = (uint32_t)(prow[i] * 128 + ((pseg[i] ^ (prow[i] & 7)) << 4));
    }

#define PREFETCH(pc) do {                                                     \
    if ((pc) < NCH) {                                                         \
        int k0 = (pc) * GKC;                                                  \
        uint32_t stb = sbase + ((pc) % 3) * STAGE_BYTES;                      \
        _Pragma("unroll")                                                     \
        for (int i = 0; i < 4; ++i) {                                         \
            cpa16(stb + poff[i],                                              \
                  A + (size_t)(row0 + prow[i]) * Kd + k0 + pseg[i] * 4, 16);  \
            int nr = col0 + prow[i];                                          \
            int ok = (nr < Nn);                                               \
            cpa16(stb + 16384 + poff[i],                                      \
                  Bt + (size_t)(ok ? nr : 0) * Kd + k0 + pseg[i] * 4,         \
                  ok ? 16 : 0);                                               \
        }                                                                     \
    }                                                                         \
    CP_COMMIT();                                                              \
} while (0)

    PREFETCH(0);
    PREFETCH(1);

    for (int c = 0; c < NCH; ++c) {
        CP_WAIT1();
        __syncthreads();
        PREFETCH(c + 2);

        const float* Af = smem + (c % 3) * 8192;
        const float* Bf = Af + 4096;

#pragma unroll
        for (int kk = 0; kk < 4; ++kk) {
            uint32_t af[2][4];
#pragma unroll
            for (int mi = 0; mi < 2; ++mi) {
                int ra = wm + mi * 16 + gid;
                int s0 = ((kk * 2) ^ (ra & 7)) << 2;
                int s1 = ((kk * 2 + 1) ^ (ra & 7)) << 2;
                int base = ra * 32 + tig;
                af[mi][0] = __float_as_uint(Af[base + s0]);
                af[mi][1] = __float_as_uint(Af[base + s0 + 256]);
                af[mi][2] = __float_as_uint(Af[base + s1]);
                af[mi][3] = __float_as_uint(Af[base + s1 + 256]);
            }
            uint32_t bf[8][2];
#pragma unroll
            for (int ni = 0; ni < 8; ++ni) {
                int rb = wn + ni * 8 + gid;
                int base = rb * 32 + tig;
                bf[ni][0] = __float_as_uint(Bf[base + (((kk * 2) ^ (rb & 7)) << 2)]);
                bf[ni][1] = __float_as_uint(Bf[base + (((kk * 2 + 1) ^ (rb & 7)) << 2)]);
            }
#pragma unroll
            for (int mi = 0; mi < 2; ++mi)
#pragma unroll
                for (int ni = 0; ni < 8; ++ni)
                    mma_tf32(acc[mi][ni], af[mi], bf[ni]);
        }
    }
#undef PREFETCH

#pragma unroll
    for (int mi = 0; mi < 2; ++mi) {
        int r0 = row0 + wm + mi * 16 + gid;
#pragma unroll
        for (int ni = 0; ni < 8; ++ni) {
            int cc = col0 + wn + ni * 8 + tig * 2;
            if (cc < Nn) {
                *(float2*)(C + (size_t)r0 * Nn + cc) =
                    make_float2(acc[mi][ni][0], acc[mi][ni][1]);
                *(float2*)(C + (size_t)(r0 + 8) * Nn + cc) =
                    make_float2(acc[mi][ni][2], acc[mi][ni][3]);
            }
        }
    }
}

// ---------------------------------------------------------------------------
// Causal depthwise conv1d, kernel 4, left pad 3 — float4 over channels.
// TOT = 2080 = 520 float4.
// ---------------------------------------------------------------------------
#define TOT4 (TOT / 4)
__global__ __launch_bounds__(256) void conv_kernel(
    const float4* __restrict__ z, const float4* __restrict__ wc,
    const float4* __restrict__ bc, float4* __restrict__ zc)
{
    int idx = blockIdx.x * 256 + threadIdx.x;
    const int total = BB * LL * TOT4;
    if (idx >= total) return;
    int c  = idx % TOT4;
    int bl = idx / TOT4;
    int l  = bl % LL;

    float4 acc = bc[c];
#pragma unroll
    for (int jk = 0; jk < CONVK; ++jk) {
        int ls = l - 3 + jk;
        if (ls >= 0) {
            float4 w = wc[jk * TOT4 + c];
            float4 v = z[(size_t)(bl - 3 + jk) * TOT4 + c];
            acc.x += w.x * v.x; acc.y += w.y * v.y;
            acc.z += w.z * v.z; acc.w += w.w * v.w;
        }
    }
    zc[idx] = acc;
}

// ---------------------------------------------------------------------------
// Shared per-thread scan preamble
// ---------------------------------------------------------------------------
struct ScanConst {
    float theta_t, w0, w1, w2, ss, rate;
    bool decay;
};

__device__ __forceinline__ ScanConst scan_consts(
    int k, int j, const float* theta, const float* dslopes,
    const float* aslopes, const float* sscale, const float* dlogits)
{
    ScanConst sc;
    sc.theta_t = theta[k * (HD * MT) + j];
    float dl0 = dlogits[0], dl1 = dlogits[1], dl2 = dlogits[2];
    float mx = fmaxf(dl0, fmaxf(dl1, dl2));
    float e0 = __expf(dl0 - mx), e1 = __expf(dl1 - mx), e2 = __expf(dl2 - mx);
    float dinv = 1.0f / (e0 + e1 + e2);
    sc.w0 = e0 * dinv; sc.w1 = e1 * dinv; sc.w2 = e2 * dinv;
    sc.ss = sscale[k];
    sc.decay = (k < KH - ANCHOR);
    float slope = sc.decay ? dslopes[k] : aslopes[k - (KH - ANCHOR)];
    sc.rate = logf(1.0f + expf(slope));
    return sc;
}

// tw maintained by caller via geometric recurrence.
__device__ __forceinline__ void scan_step(
    const ScanConst& sc, float xv, float sv, float tw,
    float& accRe, float& accIm, float& accDen)
{
    float parg = fminf(fmaxf(sc.ss * sv, -20.0f), 20.0f);
    float p = __expf(parg);
    float pw = p * tw;
    float phi = xv * sc.theta_t;
    float sbv, cbv;
    __sincosf(phi, &sbv, &cbv);
    float poly = sc.w0 + sc.w1 * xv - sc.w2 * xv * xv;
    float ppw = pw * poly;
    accDen += pw;
    accRe  += ppw * cbv;
    accIm  += ppw * sbv;
}

__device__ __forceinline__ void tw_init(const ScanConst& sc, int lstart,
                                        float& tw, float& twm)
{
    if (sc.decay) {
        tw  = __expf(-sc.rate * (float)(LL - 1 - lstart));
        twm = __expf(sc.rate);
    } else {
        tw  = __expf(-sc.rate * (float)lstart);
        twm = __expf(-sc.rate);
    }
}

// ---------------------------------------------------------------------------
// Scan pass 1: per-chunk lane sums (R7 structure). grid = B*K*NC, block 128.
// ---------------------------------------------------------------------------
__global__ __launch_bounds__(128) void scan_part1(
    const float* __restrict__ zc, const float* __restrict__ theta,
    const float* __restrict__ dslopes, const float* __restrict__ aslopes,
    const float* __restrict__ sscale, const float* __restrict__ dlogits,
    float* __restrict__ part)
{
    __shared__ float sxv[TT * 32];
    __shared__ float ssv[TT];

    const int chunk = blockIdx.x % NC;
    const int bk    = blockIdx.x / NC;
    const int k  = bk % KH;
    const int bb = bk / KH;
    const int tid = threadIdx.x;
    const int j = tid, h = j >> 2;

    const ScanConst sc = scan_consts(k, j, theta, dslopes, aslopes, sscale, dlogits);
    float tw, twm;
    tw_init(sc, chunk * CL, tw, twm);

    float accRe = 0.0f, accIm = 0.0f, accDen = 0.0f;
    const size_t baserow = (size_t)bb * LL;

    for (int l0 = chunk * CL; l0 < chunk * CL + CL; l0 += TT) {
        __syncthreads();
        {
            int v = tid;
            int t = v >> 5, hh = v & 31;
            sxv[v] = zc[(baserow + l0 + t) * (size_t)TOT + (size_t)k * HD + hh];
            v = tid + 128; t = v >> 5; hh = v & 31;
            sxv[v] = zc[(baserow + l0 + t) * (size_t)TOT + (size_t)k * HD + hh];
            if (tid < TT)
                ssv[tid] = zc[(baserow + l0 + tid) * (size_t)TOT + 2 * DM + k];
        }
        __syncthreads();
#pragma unroll
        for (int t = 0; t < TT; ++t) {
            scan_step(sc, sxv[t * 32 + h], ssv[t], tw, accRe, accIm, accDen);
            tw *= twm;
        }
    }

    float* p = part + (size_t)blockIdx.x * 384;
    p[j] = accRe; p[128 + j] = accIm; p[256 + j] = accDen;
}

// ---------------------------------------------------------------------------
// Scan pass 2: exclusive prefix over chunks, in place. grid = B*K, block 128.
// ---------------------------------------------------------------------------
__global__ __launch_bounds__(128) void scan_part2(float* __restrict__ part)
{
    const int bk = blockIdx.x;
    const int j = threadIdx.x;
    float rRe = 0.0f, rIm = 0.0f, rDen = 0.0f;
    for (int c = 0; c < NC; ++c) {
        float* p = part + ((size_t)bk * NC + c) * 384;
        float tRe = p[j], tIm = p[128 + j], tDen = p[256 + j];
        p[j] = rRe; p[128 + j] = rIm; p[256 + j] = rDen;
        rRe += tRe; rIm += tIm; rDen += tDen;
    }
}

// ---------------------------------------------------------------------------
// Scan pass 3 (fused): scan + joint RMS norm (shuffle-reduced, no ssq smem)
// + in-SMEM projection GEMM (mma.sync) + SiLU gate. Writes g directly.
// grid = B*K*NC, block = 128. SMEM 53,184 B -> 4 CTAs/SM.
// ---------------------------------------------------------------------------
#define P3_WS    0
#define P3_AS    (32 * 260)                 // 8320
#define P3_SXV   (P3_AS + 16 * 260)         // 12480
#define P3_SGV   (P3_SXV + TT * 32)         // 12736
#define P3_SSV   (P3_SGV + 16 * 32)         // 13248
#define P3_SRSQ  (P3_SSV + TT)              // 13256
#define P3_SPART (P3_SRSQ + TT)             // 13264
#define P3_SMEM  ((P3_SPART + TT * 4) * 4)  // 53184 bytes

__global__ __launch_bounds__(128) void scan_part3(
    const float* __restrict__ zc, const float* __restrict__ theta,
    const float* __restrict__ dslopes, const float* __restrict__ aslopes,
    const float* __restrict__ sscale, const float* __restrict__ dlogits,
    const float* __restrict__ nscale, const float* __restrict__ Wp,
    const float* __restrict__ part, float* __restrict__ g_out)
{
    extern __shared__ float sm[];
    float* Ws    = sm + P3_WS;
    float* As    = sm + P3_AS;
    float* sxv   = sm + P3_SXV;
    float* sgv   = sm + P3_SGV;
    float* ssv   = sm + P3_SSV;
    float* srsq  = sm + P3_SRSQ;
    float* spart = sm + P3_SPART;   // [t*4 + warp]

    const int chunk = blockIdx.x % NC;
    const int bk    = blockIdx.x / NC;
    const int k  = bk % KH;
    const int bb = bk / KH;
    const int tid = threadIdx.x;
    const int j = tid, h = j >> 2;
    const int lane = tid & 31;
    const int warp = tid >> 5;
    const int gid = lane >> 2, tig = lane & 3;

    const ScanConst sc = scan_consts(k, j, theta, dslopes, aslopes, sscale, dlogits);
    const float ns_re = nscale[j];
    const float ns_im = nscale[HD * MT + j];
    float tw, twm;
    tw_init(sc, chunk * CL, tw, twm);

    // load projection weights (32 x 256) into padded smem
    for (int i = tid; i < 32 * 256; i += 128) {
        int row = i >> 8, col = i & 255;
        Ws[row * 260 + col] = Wp[i];
    }

    const float* pfx = part + (size_t)blockIdx.x * 384;
    float accRe = pfx[j], accIm = pfx[128 + j], accDen = pfx[256 + j];
    const size_t baserow = (size_t)bb * LL;

    for (int grp = 0; grp < CL / 16; ++grp) {
        const int gl0 = chunk * CL + grp * 16;

#pragma unroll
        for (int sub = 0; sub < 2; ++sub) {
            const int l0 = gl0 + sub * TT;
            __syncthreads();
            {
                int v = tid;
                int t = v >> 5, hh = v & 31;
                size_t rowA = (baserow + l0 + t) * (size_t)TOT;
                sxv[v] = zc[rowA + (size_t)k * HD + hh];
                sgv[(sub * TT + t) * 32 + hh] = zc[rowA + DM + (size_t)k * HD + hh];
                v = tid + 128; t = v >> 5; hh = v & 31;
                size_t rowB = (baserow + l0 + t) * (size_t)TOT;
                sxv[v] = zc[rowB + (size_t)k * HD + hh];
                sgv[(sub * TT + t) * 32 + hh] = zc[rowB + DM + (size_t)k * HD + hh];
                if (tid < TT)
                    ssv[tid] = zc[(baserow + l0 + tid) * (size_t)TOT + 2 * DM + k];
            }
            __syncthreads();

            float re[TT], im[TT];
#pragma unroll
            for (int t = 0; t < TT; ++t) {
                scan_step(sc, sxv[t * 32 + h], ssv[t], tw, accRe, accIm, accDen);
                tw *= twm;
                float invd = 1.0f / fmaxf(accDen, 1e-4f);
                re[t] = accRe * invd;
                im[t] = accIm * invd;
                // warp-level reduce of re^2+im^2 (partial per warp)
                float v = re[t] * re[t] + im[t] * im[t];
#pragma unroll
                for (int off = 16; off; off >>= 1)
                    v += __shfl_xor_sync(0xffffffffu, v, off);
                if (lane == 0) spart[t * 4 + warp] = v;
            }
            __syncthreads();

            if (tid < TT) {
                float v = spart[tid * 4] + spart[tid * 4 + 1]
                        + spart[tid * 4 + 2] + spart[tid * 4 + 3];
                srsq[tid] = rsqrtf(v * (1.0f / (2.0f * HD * MT)) + 1e-5f);
            }
            __syncthreads();

#pragma unroll
            for (int t = 0; t < TT; ++t) {
                float r = srsq[t];
                int row = sub * TT + t;
                As[row * 260 + j]       = f2tf_f(re[t] * r * ns_re);
                As[row * 260 + 128 + j] = f2tf_f(im[t] * r * ns_im);
            }
        }
        __syncthreads();   // As tile (16 x 256) complete

        // projection: C(16 x 32) = As(16 x 256) @ Ws(32 x 256)^T
        float acc[4] = {0.0f, 0.0f, 0.0f, 0.0f};
#pragma unroll
        for (int ks = 0; ks < 32; ++ks) {
            int kb = ks * 8;
            uint32_t af[4], bf[2];
            int abase = gid * 260 + kb + tig;
            af[0] = __float_as_uint(As[abase]);
            af[1] = __float_as_uint(As[abase + 8 * 260]);
            af[2] = __float_as_uint(As[abase + 4]);
            af[3] = __float_as_uint(As[abase + 8 * 260 + 4]);
            int bbase = (warp * 8 + gid) * 260 + kb + tig;
            bf[0] = __float_as_uint(Ws[bbase]);
            bf[1] = __float_as_uint(Ws[bbase + 4]);
            mma_tf32(acc, af, bf);
        }

        // epilogue: gate + tf32 round + store to g
#pragma unroll
        for (int rg = 0; rg < 2; ++rg) {
            int m = gid + rg * 8;           // step within group
            int l = gl0 + m;
            int hh = warp * 8 + tig * 2;
            float gz0 = sgv[m * 32 + hh];
            float gz1 = sgv[m * 32 + hh + 1];
            float s0 = gz0 / (1.0f + __expf(-gz0));
            float s1 = gz1 / (1.0f + __expf(-gz1));
            *(float2*)(g_out + (baserow + l) * (size_t)DM + (size_t)k * HD + hh) =
                make_float2(f2tf_f(acc[rg * 2 + 0] * s0),
                            f2tf_f(acc[rg * 2 + 1] * s1));
        }
    }
}

// ---------------------------------------------------------------------------
extern "C" void kernel_launch(void* const* d_in, const int* in_sizes, int n_in,
                              void* d_out, int out_size)
{
    const float* x       = (const float*)d_in[0];
    const float* W_in    = (const float*)d_in[1];
    const float* w_conv  = (const float*)d_in[2];
    const float* b_conv  = (const float*)d_in[3];
    const float* theta   = (const float*)d_in[4];
    const float* dslopes = (const float*)d_in[5];
    const float* aslopes = (const float*)d_in[6];
    const float* sscale  = (const float*)d_in[7];
    const float* dlogits = (const float*)d_in[8];
    const float* nscale  = (const float*)d_in[9];
    const float* W_re    = (const float*)d_in[10];
    const float* W_im    = (const float*)d_in[11];
    const float* W_out   = (const float*)d_in[12];
    float* out = (float*)d_out;

    float *pz, *pzc, *pg, *px32, *pbt1, *pbt2, *pbtp, *ppart;
    cudaGetSymbolAddress((void**)&pz,    g_z);
    cudaGetSymbolAddress((void**)&pzc,   g_zc);
    cudaGetSymbolAddress((void**)&pg,    g_g);
    cudaGetSymbolAddress((void**)&px32,  g_x32);
    cudaGetSymbolAddress((void**)&pbt1,  g_bt1);
    cudaGetSymbolAddress((void**)&pbt2,  g_bt2);
    cudaGetSymbolAddress((void**)&pbtp,  g_btp);
    cudaGetSymbolAddress((void**)&ppart, g_part);

    static bool attr_set = false;
    if (!attr_set) {
        cudaFuncSetAttribute(gemm_cp,
                             cudaFuncAttributeMaxDynamicSharedMemorySize, GEMM_SMEM);
        cudaFuncSetAttribute(scan_part3,
                             cudaFuncAttributeMaxDynamicSharedMemorySize, P3_SMEM);
        attr_set = true;
    }

    // 0) weight prep + x rounding
    transpose_k<<<dim3((TOT + 31) / 32, DM / 32), 256>>>(W_in, pbt1, DM, TOT);
    transpose_k<<<dim3(DM / 32, DM / 32), 256>>>(W_out, pbt2, DM, DM);
    proj_wprep<<<32, 256>>>(W_re, W_im, pbtp);
    {
        int n4 = BB * LL * DM / 4;
        round_tf32_k<<<(n4 + 255) / 256, 256>>>((const float4*)x, (float4*)px32, n4);
    }

    // 1) z = x @ W_in   — TF32 mma.sync, cp.async pipeline
    {
        dim3 grid((TOT + 127) / 128, (BB * LL) / 128);
        gemm_cp<<<grid, 256, GEMM_SMEM>>>(px32, pbt1, pz, BB * LL, TOT, DM);
    }
    // 2) causal depthwise conv (float4)
    {
        int total = BB * LL * TOT4;
        conv_kernel<<<(total + 255) / 256, 256>>>(
            (const float4*)pz, (const float4*)w_conv,
            (const float4*)b_conv, (float4*)pzc);
    }
    // 3) chunked parallel scan; part3 fuses RMS norm + projection + gate
    scan_part1<<<BB * KH * NC, 128>>>(pzc, theta, dslopes, aslopes,
                                      sscale, dlogits, ppart);
    scan_part2<<<BB * KH, 128>>>(ppart);
    scan_part3<<<BB * KH * NC, 128, P3_SMEM>>>(pzc, theta, dslopes, aslopes,
                                               sscale, dlogits, nscale,
                                               pbtp, ppart, pg);
    // 4) out = g @ W_out — TF32 mma.sync, cp.async pipeline
    {
        dim3 grid(DM / 128, (BB * LL) / 128);
        gemm_cp<<<grid, 256, GEMM_SMEM>>>(pg, pbt2, out, BB * LL, DM, DM);
    }
}

// round 14
// speedup vs baseline: 1.1348x; 1.0579x over previous
#include <cuda_runtime.h>
#include <cuda_bf16.h>
#include <cstdint>

// Problem constants
#define BB   4
#define LL   2048
#define DM   1024
#define KH   32        // heads
#define HD   32        // head dim
#define MT   4         // m_theta
#define TOT  2080      // 2*DM + KH
#define CONVK 4
#define ANCHOR 4
#define TT   8         // scan tile (time steps per tile)
#define NC   32        // scan chunks
#define CL   (LL / NC) // 64 steps per chunk

// Scratch (static device globals — no runtime allocation allowed)
__device__ float g_z   [BB * LL * TOT];   // x @ W_in
__device__ float g_zc  [BB * LL * TOT];   // after causal depthwise conv
__device__ float g_g   [BB * LL * DM];    // gated y (input to final GEMM), tf32-rounded
__device__ float g_x32 [BB * LL * DM];    // x rounded to tf32
__device__ float g_bt1 [TOT * DM];        // W_in^T  (2080 x 1024), K-major, tf32-rounded
__device__ float g_bt2 [DM * DM];         // W_out^T (1024 x 1024), tf32-rounded
__device__ float g_btp [32 * 256];        // [W_re;W_im]^T (32 x 256), tf32-rounded
__device__ float g_part[BB * KH * NC * 3 * 128];  // chunk partials / prefixes

// ---------------------------------------------------------------------------
// TF32 helpers
// ---------------------------------------------------------------------------
__device__ __forceinline__ uint32_t f2tf(float f) {
    uint32_t u;
    asm("cvt.rna.tf32.f32 %0, %1;" : "=r"(u) : "f"(f));
    return u;
}
__device__ __forceinline__ float f2tf_f(float f) {
    return __uint_as_float(f2tf(f));
}

__device__ __forceinline__ void mma_tf32(float* c4, const uint32_t* a4,
                                         const uint32_t* b2) {
    asm volatile(
        "mma.sync.aligned.m16n8k8.row.col.f32.tf32.tf32.f32 "
        "{%0,%1,%2,%3}, {%4,%5,%6,%7}, {%8,%9}, {%0,%1,%2,%3};"
        : "+f"(c4[0]), "+f"(c4[1]), "+f"(c4[2]), "+f"(c4[3])
        : "r"(a4[0]), "r"(a4[1]), "r"(a4[2]), "r"(a4[3]),
          "r"(b2[0]), "r"(b2[1]));
}

__device__ __forceinline__ uint32_t smem_u32(const void* p) {
    uint32_t a;
    asm("{ .reg .u64 t; cvta.to.shared.u64 t, %1; cvt.u32.u64 %0, t; }"
        : "=r"(a) : "l"(p));
    return a;
}
__device__ __forceinline__ void cpa16(uint32_t d, const void* s, int sz) {
    asm volatile("cp.async.cg.shared.global [%0], [%1], 16, %2;"
                 :: "r"(d), "l"(s), "r"(sz));
}
#define CP_COMMIT() asm volatile("cp.async.commit_group;" ::: "memory")
#define CP_WAIT1()  asm volatile("cp.async.wait_group 1;" ::: "memory")

// ---------------------------------------------------------------------------
// Round fp32 array to tf32 (RNA), vectorized.
// ---------------------------------------------------------------------------
__global__ __launch_bounds__(256) void round_tf32_k(
    const float4* __restrict__ src, float4* __restrict__ dst, int n4)
{
    int i = blockIdx.x * 256 + threadIdx.x;
    if (i < n4) {
        float4 v = src[i];
        v.x = f2tf_f(v.x); v.y = f2tf_f(v.y);
        v.z = f2tf_f(v.z); v.w = f2tf_f(v.w);
        dst[i] = v;
    }
}

// ---------------------------------------------------------------------------
// Tiled transpose with tf32 rounding: D[C][R] = round_tf32(S[R][C]^T)
// ---------------------------------------------------------------------------
__global__ __launch_bounds__(256) void transpose_k(
    const float* __restrict__ S, float* __restrict__ D, int R, int C)
{
    __shared__ float t[32][33];
    int c0 = blockIdx.x * 32, r0 = blockIdx.y * 32;
    int x = threadIdx.x & 31, y = threadIdx.x >> 5;   // 32 x 8
#pragma unroll
    for (int i = 0; i < 32; i += 8) {
        int r = r0 + y + i, c = c0 + x;
        t[y + i][x] = (r < R && c < C) ? S[(size_t)r * C + c] : 0.0f;
    }
    __syncthreads();
#pragma unroll
    for (int i = 0; i < 32; i += 8) {
        int r = c0 + y + i, c = r0 + x;
        if (r < C && c < R) D[(size_t)r * R + c] = f2tf_f(t[x][y + i]);
    }
}

// ---------------------------------------------------------------------------
// Projection weight prep: Bt(32 x 256), Bt[n][kk] = [W_re;W_im][kk][n]
// ---------------------------------------------------------------------------
__global__ __launch_bounds__(256) void proj_wprep(
    const float* __restrict__ Wre, const float* __restrict__ Wim,
    float* __restrict__ Bt)
{
    int i = blockIdx.x * 256 + threadIdx.x;
    if (i < 32 * 256) {
        int n = i >> 8, kk = i & 255;
        float v = (kk < 128) ? Wre[kk * 32 + n] : Wim[(kk - 128) * 32 + n];
        Bt[i] = f2tf_f(v);
    }
}

// ---------------------------------------------------------------------------
// TF32 tensor-core GEMM, cp.async 3-stage pipeline (frozen from R5):
//   C(M,Nn) = A(M,Kd) * Bt(Nn,Kd)^T; A and Bt pre-rounded to tf32.
// ---------------------------------------------------------------------------
#define GKC 32
#define STAGE_BYTES 32768
#define GEMM_SMEM  (3 * STAGE_BYTES)

__global__ __launch_bounds__(256, 2) void gemm_cp(
    const float* __restrict__ A, const float* __restrict__ Bt,
    float* __restrict__ C, int M, int Nn, int Kd)
{
    extern __shared__ float smem[];
    const uint32_t sbase = smem_u32(smem);
    const int tid = threadIdx.x;
    const int wid = tid >> 5, lane = tid & 31;
    const int gid = lane >> 2, tig = lane & 3;
    const int wm = (wid >> 1) * 32;
    const int wn = (wid & 1) * 64;
    const int row0 = blockIdx.y * 128;
    const int col0 = blockIdx.x * 128;
    const int NCH = Kd / GKC;

    float acc[2][8][4];
#pragma unroll
    for (int mi = 0; mi < 2; ++mi)
#pragma unroll
        for (int ni = 0; ni < 8; ++ni)
#pragma unroll
            for (int q = 0; q < 4; ++q) acc[mi][ni][q] = 0.0f;

    int prow[4], pseg[4];
    uint32_t poff[4];
#pragma unroll
    for (int i = 0; i < 4; ++i) {
        int idx = i * 256 + tid;
        prow[i] = idx >> 3;
        pseg[i] = idx & 7;
        poff[i] = (uint32_t)(prow[i] * 128 + ((pseg[i] ^ (prow[i] & 7)) << 4));
    }

#define PREFETCH(pc) do {                                                     \
    if ((pc) < NCH) {                                                         \
        int k0 = (pc) * GKC;                                                  \
        uint32_t stb = sbase + ((pc) % 3) * STAGE_BYTES;                      \
        _Pragma("unroll")                                                     \
        for (int i = 0; i < 4; ++i) {                                         \
            cpa16(stb + poff[i],                                              \
                  A + (size_t)(row0 + prow[i]) * Kd + k0 + pseg[i] * 4, 16);  \
            int nr = col0 + prow[i];                                          \
            int ok = (nr < Nn);                                               \
            cpa16(stb + 16384 + poff[i],                                      \
                  Bt + (size_t)(ok ? nr : 0) * Kd + k0 + pseg[i] * 4,         \
                  ok ? 16 : 0);                                               \
        }                                                                     \
    }                                                                         \
    CP_COMMIT();                                                              \
} while (0)

    PREFETCH(0);
    PREFETCH(1);

    for (int c = 0; c < NCH; ++c) {
        CP_WAIT1();
        __syncthreads();
        PREFETCH(c + 2);

        const float* Af = smem + (c % 3) * 8192;
        const float* Bf = Af + 4096;

#pragma unroll
        for (int kk = 0; kk < 4; ++kk) {
            uint32_t af[2][4];
#pragma unroll
            for (int mi = 0; mi < 2; ++mi) {
                int ra = wm + mi * 16 + gid;
                int s0 = ((kk * 2) ^ (ra & 7)) << 2;
                int s1 = ((kk * 2 + 1) ^ (ra & 7)) << 2;
                int base = ra * 32 + tig;
                af[mi][0] = __float_as_uint(Af[base + s0]);
                af[mi][1] = __float_as_uint(Af[base + s0 + 256]);
                af[mi][2] = __float_as_uint(Af[base + s1]);
                af[mi][3] = __float_as_uint(Af[base + s1 + 256]);
            }
            uint32_t bf[8][2];
#pragma unroll
            for (int ni = 0; ni < 8; ++ni) {
                int rb = wn + ni * 8 + gid;
                int base = rb * 32 + tig;
                bf[ni][0] = __float_as_uint(Bf[base + (((kk * 2) ^ (rb & 7)) << 2)]);
                bf[ni][1] = __float_as_uint(Bf[base + (((kk * 2 + 1) ^ (rb & 7)) << 2)]);
            }
#pragma unroll
            for (int mi = 0; mi < 2; ++mi)
#pragma unroll
                for (int ni = 0; ni < 8; ++ni)
                    mma_tf32(acc[mi][ni], af[mi], bf[ni]);
        }
    }
#undef PREFETCH

#pragma unroll
    for (int mi = 0; mi < 2; ++mi) {
        int r0 = row0 + wm + mi * 16 + gid;
#pragma unroll
        for (int ni = 0; ni < 8; ++ni) {
            int cc = col0 + wn + ni * 8 + tig * 2;
            if (cc < Nn) {
                *(float2*)(C + (size_t)r0 * Nn + cc) =
                    make_float2(acc[mi][ni][0], acc[mi][ni][1]);
                *(float2*)(C + (size_t)(r0 + 8) * Nn + cc) =
                    make_float2(acc[mi][ni][2], acc[mi][ni][3]);
            }
        }
    }
}

// ---------------------------------------------------------------------------
// Causal depthwise conv1d, kernel 4, left pad 3 — float4 over channels.
// TOT = 2080 = 520 float4.
// ---------------------------------------------------------------------------
#define TOT4 (TOT / 4)
__global__ __launch_bounds__(256) void conv_kernel(
    const float4* __restrict__ z, const float4* __restrict__ wc,
    const float4* __restrict__ bc, float4* __restrict__ zc)
{
    int idx = blockIdx.x * 256 + threadIdx.x;
    const int total = BB * LL * TOT4;
    if (idx >= total) return;
    int c  = idx % TOT4;
    int bl = idx / TOT4;
    int l  = bl % LL;

    float4 acc = bc[c];
#pragma unroll
    for (int jk = 0; jk < CONVK; ++jk) {
        int ls = l - 3 + jk;
        if (ls >= 0) {
            float4 w = wc[jk * TOT4 + c];
            float4 v = z[(size_t)(bl - 3 + jk) * TOT4 + c];
            acc.x += w.x * v.x; acc.y += w.y * v.y;
            acc.z += w.z * v.z; acc.w += w.w * v.w;
        }
    }
    zc[idx] = acc;
}

// ---------------------------------------------------------------------------
// Shared per-thread scan preamble
// ---------------------------------------------------------------------------
struct ScanConst {
    float theta_t, w0, w1, w2, ss, rate;
    bool decay;
};

__device__ __forceinline__ ScanConst scan_consts(
    int k, int j, const float* theta, const float* dslopes,
    const float* aslopes, const float* sscale, const float* dlogits)
{
    ScanConst sc;
    sc.theta_t = theta[k * (HD * MT) + j];
    float dl0 = dlogits[0], dl1 = dlogits[1], dl2 = dlogits[2];
    float mx = fmaxf(dl0, fmaxf(dl1, dl2));
    float e0 = __expf(dl0 - mx), e1 = __expf(dl1 - mx), e2 = __expf(dl2 - mx);
    float dinv = 1.0f / (e0 + e1 + e2);
    sc.w0 = e0 * dinv; sc.w1 = e1 * dinv; sc.w2 = e2 * dinv;
    sc.ss = sscale[k];
    sc.decay = (k < KH - ANCHOR);
    float slope = sc.decay ? dslopes[k] : aslopes[k - (KH - ANCHOR)];
    sc.rate = logf(1.0f + expf(slope));
    return sc;
}

// tw maintained by caller via geometric recurrence.
__device__ __forceinline__ void scan_step(
    const ScanConst& sc, float xv, float sv, float tw,
    float& accRe, float& accIm, float& accDen)
{
    float parg = fminf(fmaxf(sc.ss * sv, -20.0f), 20.0f);
    float p = __expf(parg);
    float pw = p * tw;
    float phi = xv * sc.theta_t;
    float sbv, cbv;
    __sincosf(phi, &sbv, &cbv);
    float poly = sc.w0 + sc.w1 * xv - sc.w2 * xv * xv;
    float ppw = pw * poly;
    accDen += pw;
    accRe  += ppw * cbv;
    accIm  += ppw * sbv;
}

__device__ __forceinline__ void tw_init(const ScanConst& sc, int lstart,
                                        float& tw, float& twm)
{
    if (sc.decay) {
        tw  = __expf(-sc.rate * (float)(LL - 1 - lstart));
        twm = __expf(sc.rate);
    } else {
        tw  = __expf(-sc.rate * (float)lstart);
        twm = __expf(-sc.rate);
    }
}

// ---------------------------------------------------------------------------
// Scan pass 1: per-chunk lane sums. grid = B*K*NC, block = 128.
// ---------------------------------------------------------------------------
__global__ __launch_bounds__(128) void scan_part1(
    const float* __restrict__ zc, const float* __restrict__ theta,
    const float* __restrict__ dslopes, const float* __restrict__ aslopes,
    const float* __restrict__ sscale, const float* __restrict__ dlogits,
    float* __restrict__ part)
{
    __shared__ float sxv[TT * 32];
    __shared__ float ssv[TT];

    const int chunk = blockIdx.x % NC;
    const int bk    = blockIdx.x / NC;
    const int k  = bk % KH;
    const int bb = bk / KH;
    const int tid = threadIdx.x;
    const int j = tid, h = j >> 2;

    const ScanConst sc = scan_consts(k, j, theta, dslopes, aslopes, sscale, dlogits);
    float tw, twm;
    tw_init(sc, chunk * CL, tw, twm);

    float accRe = 0.0f, accIm = 0.0f, accDen = 0.0f;
    const size_t baserow = (size_t)bb * LL;

    for (int l0 = chunk * CL; l0 < chunk * CL + CL; l0 += TT) {
        __syncthreads();
        {
            int v = tid;
            int t = v >> 5, hh = v & 31;
            sxv[v] = zc[(baserow + l0 + t) * (size_t)TOT + (size_t)k * HD + hh];
            v = tid + 128; t = v >> 5; hh = v & 31;
            sxv[v] = zc[(baserow + l0 + t) * (size_t)TOT + (size_t)k * HD + hh];
            if (tid < TT)
                ssv[tid] = zc[(baserow + l0 + tid) * (size_t)TOT + 2 * DM + k];
        }
        __syncthreads();
#pragma unroll
        for (int t = 0; t < TT; ++t) {
            scan_step(sc, sxv[t * 32 + h], ssv[t], tw, accRe, accIm, accDen);
            tw *= twm;
        }
    }

    float* p = part + (size_t)blockIdx.x * 384;
    p[j] = accRe; p[128 + j] = accIm; p[256 + j] = accDen;
}

// ---------------------------------------------------------------------------
// Scan pass 2: exclusive prefix over chunks, in place. grid = B*K, block 128.
// ---------------------------------------------------------------------------
__global__ __launch_bounds__(128) void scan_part2(float* __restrict__ part)
{
    const int bk = blockIdx.x;
    const int j = threadIdx.x;
    float rRe = 0.0f, rIm = 0.0f, rDen = 0.0f;
    for (int c = 0; c < NC; ++c) {
        float* p = part + ((size_t)bk * NC + c) * 384;
        float tRe = p[j], tIm = p[128 + j], tDen = p[256 + j];
        p[j] = rRe; p[128 + j] = rIm; p[256 + j] = rDen;
        rRe += tRe; rIm += tIm; rDen += tDen;
    }
}

// ---------------------------------------------------------------------------
// Scan pass 3 (fused): scan + joint RMS norm + in-SMEM projection GEMM
// (mma.sync) + SiLU gate. Writes g directly. grid = B*K*NC, block = 128.
//
// SMEM (floats, stride 260 to kill bank conflicts):
//   Ws   [32 x 260]  projection weights (32 rows x 256 cols used)
//   As   [16 x 260]  normalized [re|im] tile for a 16-step group
//   ssq  [TT * 128], sxv [TT*32], sgv [16*32], ssv [TT], srsq [TT]
// ---------------------------------------------------------------------------
#define P3_WS   0
#define P3_AS   (32 * 260)                 // 8320
#define P3_SSQ  (P3_AS + 16 * 260)         // 12480
#define P3_SXV  (P3_SSQ + TT * 128)        // 13504
#define P3_SGV  (P3_SXV + TT * 32)         // 13760
#define P3_SSV  (P3_SGV + 16 * 32)         // 14272
#define P3_SRSQ (P3_SSV + TT)              // 14280
#define P3_SMEM ((P3_SRSQ + TT) * 4)       // 57152 bytes

__global__ __launch_bounds__(128) void scan_part3(
    const float* __restrict__ zc, const float* __restrict__ theta,
    const float* __restrict__ dslopes, const float* __restrict__ aslopes,
    const float* __restrict__ sscale, const float* __restrict__ dlogits,
    const float* __restrict__ nscale, const float* __restrict__ Wp,
    const float* __restrict__ part, float* __restrict__ g_out)
{
    extern __shared__ float sm[];
    float* Ws   = sm + P3_WS;
    float* As   = sm + P3_AS;
    float* ssq  = sm + P3_SSQ;
    float* sxv  = sm + P3_SXV;
    float* sgv  = sm + P3_SGV;
    float* ssv  = sm + P3_SSV;
    float* srsq = sm + P3_SRSQ;

    const int chunk = blockIdx.x % NC;
    const int bk    = blockIdx.x / NC;
    const int k  = bk % KH;
    const int bb = bk / KH;
    const int tid = threadIdx.x;
    const int j = tid, h = j >> 2;
    const int lane = tid & 31;
    const int warp = tid >> 5;
    const int gid = lane >> 2, tig = lane & 3;

    const ScanConst sc = scan_consts(k, j, theta, dslopes, aslopes, sscale, dlogits);
    const float ns_re = nscale[j];
    const float ns_im = nscale[HD * MT + j];
    float tw, twm;
    tw_init(sc, chunk * CL, tw, twm);

    // load projection weights (32 x 256) into padded smem
    for (int i = tid; i < 32 * 256; i += 128) {
        int row = i >> 8, col = i & 255;
        Ws[row * 260 + col] = Wp[i];
    }

    const float* pfx = part + (size_t)blockIdx.x * 384;
    float accRe = pfx[j], accIm = pfx[128 + j], accDen = pfx[256 + j];
    const size_t baserow = (size_t)bb * LL;

    for (int grp = 0; grp < CL / 16; ++grp) {
        const int gl0 = chunk * CL + grp * 16;

#pragma unroll
        for (int sub = 0; sub < 2; ++sub) {
            const int l0 = gl0 + sub * TT;
            __syncthreads();
            {
                int v = tid;
                int t = v >> 5, hh = v & 31;
                size_t rowA = (baserow + l0 + t) * (size_t)TOT;
                sxv[v] = zc[rowA + (size_t)k * HD + hh];
                sgv[(sub * TT + t) * 32 + hh] = zc[rowA + DM + (size_t)k * HD + hh];
                v = tid + 128; t = v >> 5; hh = v & 31;
                size_t rowB = (baserow + l0 + t) * (size_t)TOT;
                sxv[v] = zc[rowB + (size_t)k * HD + hh];
                sgv[(sub * TT + t) * 32 + hh] = zc[rowB + DM + (size_t)k * HD + hh];
                if (tid < TT)
                    ssv[tid] = zc[(baserow + l0 + tid) * (size_t)TOT + 2 * DM + k];
            }
            __syncthreads();

            float re[TT], im[TT];
#pragma unroll
            for (int t = 0; t < TT; ++t) {
                scan_step(sc, sxv[t * 32 + h], ssv[t], tw, accRe, accIm, accDen);
                tw *= twm;
                float invd = 1.0f / fmaxf(accDen, 1e-4f);
                re[t] = accRe * invd;
                im[t] = accIm * invd;
                ssq[t * 128 + j] = re[t] * re[t] + im[t] * im[t];
            }
            __syncthreads();

            {
                int tt = warp * 2;
#pragma unroll
                for (int q = 0; q < 2; ++q, ++tt) {
                    float v = ssq[tt * 128 + lane] + ssq[tt * 128 + lane + 32]
                            + ssq[tt * 128 + lane + 64] + ssq[tt * 128 + lane + 96];
#pragma unroll
                    for (int off = 16; off; off >>= 1)
                        v += __shfl_xor_sync(0xffffffffu, v, off);
                    if (lane == 0)
                        srsq[tt] = rsqrtf(v * (1.0f / (2.0f * HD * MT)) + 1e-5f);
                }
            }
            __syncthreads();

#pragma unroll
            for (int t = 0; t < TT; ++t) {
                float r = srsq[t];
                int row = sub * TT + t;
                As[row * 260 + j]       = f2tf_f(re[t] * r * ns_re);
                As[row * 260 + 128 + j] = f2tf_f(im[t] * r * ns_im);
            }
        }
        __syncthreads();   // As tile (16 x 256) complete

        // projection: C(16 x 32) = As(16 x 256) @ Ws(32 x 256)^T
        float acc[4] = {0.0f, 0.0f, 0.0f, 0.0f};
#pragma unroll
        for (int ks = 0; ks < 32; ++ks) {
            int kb = ks * 8;
            uint32_t af[4], bf[2];
            int abase = gid * 260 + kb + tig;
            af[0] = __float_as_uint(As[abase]);
            af[1] = __float_as_uint(As[abase + 8 * 260]);
            af[2] = __float_as_uint(As[abase + 4]);
            af[3] = __float_as_uint(As[abase + 8 * 260 + 4]);
            int bbase = (warp * 8 + gid) * 260 + kb + tig;
            bf[0] = __float_as_uint(Ws[bbase]);
            bf[1] = __float_as_uint(Ws[bbase + 4]);
            mma_tf32(acc, af, bf);
        }

        // epilogue: gate + tf32 round + store to g
#pragma unroll
        for (int rg = 0; rg < 2; ++rg) {
            int m = gid + rg * 8;           // step within group
            int l = gl0 + m;
            int hh = warp * 8 + tig * 2;
            float gz0 = sgv[m * 32 + hh];
            float gz1 = sgv[m * 32 + hh + 1];
            float s0 = gz0 / (1.0f + __expf(-gz0));
            float s1 = gz1 / (1.0f + __expf(-gz1));
            *(float2*)(g_out + (baserow + l) * (size_t)DM + (size_t)k * HD + hh) =
                make_float2(f2tf_f(acc[rg * 2 + 0] * s0),
                            f2tf_f(acc[rg * 2 + 1] * s1));
        }
    }
}

// ---------------------------------------------------------------------------
extern "C" void kernel_launch(void* const* d_in, const int* in_sizes, int n_in,
                              void* d_out, int out_size)
{
    const float* x       = (const float*)d_in[0];
    const float* W_in    = (const float*)d_in[1];
    const float* w_conv  = (const float*)d_in[2];
    const float* b_conv  = (const float*)d_in[3];
    const float* theta   = (const float*)d_in[4];
    const float* dslopes = (const float*)d_in[5];
    const float* aslopes = (const float*)d_in[6];
    const float* sscale  = (const float*)d_in[7];
    const float* dlogits = (const float*)d_in[8];
    const float* nscale  = (const float*)d_in[9];
    const float* W_re    = (const float*)d_in[10];
    const float* W_im    = (const float*)d_in[11];
    const float* W_out   = (const float*)d_in[12];
    float* out = (float*)d_out;

    float *pz, *pzc, *pg, *px32, *pbt1, *pbt2, *pbtp, *ppart;
    cudaGetSymbolAddress((void**)&pz,    g_z);
    cudaGetSymbolAddress((void**)&pzc,   g_zc);
    cudaGetSymbolAddress((void**)&pg,    g_g);
    cudaGetSymbolAddress((void**)&px32,  g_x32);
    cudaGetSymbolAddress((void**)&pbt1,  g_bt1);
    cudaGetSymbolAddress((void**)&pbt2,  g_bt2);
    cudaGetSymbolAddress((void**)&pbtp,  g_btp);
    cudaGetSymbolAddress((void**)&ppart, g_part);

    static bool attr_set = false;
    if (!attr_set) {
        cudaFuncSetAttribute(gemm_cp,
                             cudaFuncAttributeMaxDynamicSharedMemorySize, GEMM_SMEM);
        cudaFuncSetAttribute(scan_part3,
                             cudaFuncAttributeMaxDynamicSharedMemorySize, P3_SMEM);
        attr_set = true;
    }

    // 0) weight prep + x rounding
    transpose_k<<<dim3((TOT + 31) / 32, DM / 32), 256>>>(W_in, pbt1, DM, TOT);
    transpose_k<<<dim3(DM / 32, DM / 32), 256>>>(W_out, pbt2, DM, DM);
    proj_wprep<<<32, 256>>>(W_re, W_im, pbtp);
    {
        int n4 = BB * LL * DM / 4;
        round_tf32_k<<<(n4 + 255) / 256, 256>>>((const float4*)x, (float4*)px32, n4);
    }

    // 1) z = x @ W_in   — TF32 mma.sync, cp.async pipeline
    {
        dim3 grid((TOT + 127) / 128, (BB * LL) / 128);
        gemm_cp<<<grid, 256, GEMM_SMEM>>>(px32, pbt1, pz, BB * LL, TOT, DM);
    }
    // 2) causal depthwise conv (float4)
    {
        int total = BB * LL * TOT4;
        conv_kernel<<<(total + 255) / 256, 256>>>(
            (const float4*)pz, (const float4*)w_conv,
            (const float4*)b_conv, (float4*)pzc);
    }
    // 3) chunked parallel scan; part3 fuses RMS norm + projection + gate
    scan_part1<<<BB * KH * NC, 128>>>(pzc, theta, dslopes, aslopes,
                                      sscale, dlogits, ppart);
    scan_part2<<<BB * KH, 128>>>(ppart);
    scan_part3<<<BB * KH * NC, 128, P3_SMEM>>>(pzc, theta, dslopes, aslopes,
                                               sscale, dlogits, nscale,
                                               pbtp, ppart, pg);
    // 4) out = g @ W_out — TF32 mma.sync, cp.async pipeline
    {
        dim3 grid(DM / 128, (BB * LL) / 128);
        gemm_cp<<<grid, 256, GEMM_SMEM>>>(pg, pbt2, out, BB * LL, DM, DM);
    }
}